// round 9
// baseline (speedup 1.0000x reference)
#include <cuda_runtime.h>

// GeneralMechanismODE — single-touch stream (96 B in, 32 B out per row).
// R9: R7 config (block 128, .cs loads for rates, .wt stores — best proven:
// 28.7us) upgraded to Blackwell 256-bit global accesses for the 32 B rows:
//   y row  : 1x ld.global.v8.f32   (was 2x LDG.128)
//   out row: 1x st.global.wt.v8.f32 (was 2x STG.128)
// Same traffic, fewer memory instructions and L1tex wavefronts per warp.

__global__ __launch_bounds__(128) void ode_kernel9(
    const float* __restrict__ y,     // B x 8
    const float4* __restrict__ kf,   // B float4
    const float4* __restrict__ kr,   // B float4
    float* __restrict__ out,         // B x 8
    int B)
{
    int b = blockIdx.x * blockDim.x + threadIdx.x;
    if (b >= B) return;

    // One 256-bit load for the whole y row (32-byte aligned).
    float y0, y1, y2, y3, y4, y5, y6, y7;
    asm volatile(
        "ld.global.v8.f32 {%0, %1, %2, %3, %4, %5, %6, %7}, [%8];"
        : "=f"(y0), "=f"(y1), "=f"(y2), "=f"(y3),
          "=f"(y4), "=f"(y5), "=f"(y6), "=f"(y7)
        : "l"(y + (size_t)b * 8));

    float4 f = __ldcs(&kf[b]);
    float4 r = __ldcs(&kr[b]);

    float v0 = f.x * y0 * y4 - r.x * y1;        // kf0*E*A  - kr0*EA
    float v1 = f.y * y1 * y5 - r.y * y3;        // kf1*EA*B - kr1*EAB
    float v2 = f.z * y3      - r.z * y2 * y6;   // kf2*EAB  - kr2*EQ*P
    float v3 = f.w * y2      - r.w * y0 * y7;   // kf3*EQ   - kr3*E*Q

    float d0 = v3 - v0;   // dE
    float d1 = v0 - v1;   // dEA
    float d2 = v2 - v3;   // dEQ
    float d3 = v1 - v2;   // dEAB
    float d4 = -v0;       // dA
    float d5 = -v1;       // dB
    float d6 = v2;        // dP
    float d7 = v3;        // dQ

    // One 256-bit write-through store for the whole output row.
    asm volatile(
        "st.global.wt.v8.f32 [%0], {%1, %2, %3, %4, %5, %6, %7, %8};"
        :
        : "l"(out + (size_t)b * 8),
          "f"(d0), "f"(d1), "f"(d2), "f"(d3),
          "f"(d4), "f"(d5), "f"(d6), "f"(d7)
        : "memory");
}

extern "C" void kernel_launch(void* const* d_in, const int* in_sizes, int n_in,
                              void* d_out, int out_size)
{
    // metadata order: t (1), y (B*8), forward_rates (B*4), reverse_rates (B*4)
    const float*  y  = (const float*)d_in[1];
    const float4* kf = (const float4*)d_in[2];
    const float4* kr = (const float4*)d_in[3];
    float* out = (float*)d_out;

    int B = in_sizes[1] / 8;
    int threads = 128;
    int blocks = (B + threads - 1) / threads;
    ode_kernel9<<<blocks, threads>>>(y, kf, kr, out, B);
}